// round 5
// baseline (speedup 1.0000x reference)
#include <cuda_runtime.h>

// DynamicLIF persistent kernel for GB300 (sm_103a), round 5.
// Base = R1 (512 blocks x 256 thr, register-resident mem, 78.5us).
// KEY CHANGE: the MLP input S_c(t) = sum(tau*prev + x) is factorized as
//   S_c(t) = tau_t * P_c(t-1) + X_c(t)
// where X_c(t) = sum(x_t) is tau-FREE (published right after the load pass,
// before the store phase) and P_c(t-1) = sum(reset mem) was published during
// step t-1's store phase. Every block then computes tau_{t+1} locally from
// global X/P -- identical values everywhere, no leader, no release hop.
// The only cross-block wait per step is cntX reaching 16 blocks, and the
// 16.7MB/step store burst overlaps that wait.

#define NB 32          // batch
#define NT 8           // time steps
#define NC 128         // channels
#define HW_ 1024       // H*W
#define CR 32          // C / red
#define THREADS 256
#define RPB 8          // float4 slices per thread (8 channels per block)
#define BPB 16         // blocks per batch
#define NBLOCKS (NB * BPB)   // 512
#define PUBS (BPB * RPB)     // 128 count-releases per batch per step

__device__ float    g_X[2][NB * NC];   // X sums, double buffered (skew <= 2)
__device__ float    g_P[4][NB * NC];   // P sums, quad buffered (skew <= 2 w/ margin)
__device__ unsigned g_cntX[NB];        // monotonic across steps AND graph replays

__device__ __forceinline__ unsigned ld_acquire(const unsigned* p) {
    unsigned v;
    asm volatile("ld.acquire.gpu.global.u32 %0, [%1];" : "=r"(v) : "l"(p));
    return v;
}
__device__ __forceinline__ void red_release_add(unsigned* p, unsigned v) {
    asm volatile("red.release.gpu.global.add.u32 [%0], %1;" :: "l"(p), "r"(v));
}

__global__ void __launch_bounds__(THREADS, 4)
lif_kernel(const float* __restrict__ x,
           const float* __restrict__ w1,
           const float* __restrict__ b1,
           const float* __restrict__ w2,
           const float* __restrict__ b2,
           float* __restrict__ out)
{
    __shared__ float s_w1[CR * NC];    // 16 KB: every block runs the MLP
    __shared__ float s_warpX[8][RPB];
    __shared__ float s_warpP[8][RPB];
    __shared__ float s_mean[NC];
    __shared__ float s_tau;

    const int tid = threadIdx.x;
    const int blk = blockIdx.x;
    const int b   = blk >> 4;          // batch
    const int sub = blk & 15;          // sub-block within batch
    const int lane = tid & 31;
    const int warp = tid >> 5;

    // Cache w1 for the local MLP.
    #pragma unroll
    for (int i = 0; i < (CR * NC) / THREADS; i++)
        s_w1[i * THREADS + tid] = w1[i * THREADS + tid];
    __syncthreads();

    // Monotonic counter base: stable at launch (replays serialize).
    unsigned base_cnt = 0;
    if (tid == 0) base_cnt = *(volatile unsigned*)&g_cntX[b];

    float tau = 0.5f;                  // TAU0
    float4 mem[RPB];
    #pragma unroll
    for (int i = 0; i < RPB; i++) mem[i] = make_float4(0.f, 0.f, 0.f, 0.f);

    // This block owns channels [sub*RPB, sub*RPB+RPB) of batch b, all HW.
    const size_t row_base = ((size_t)b * NT * NC + (size_t)sub * RPB) * HW_;

    for (int t = 0; t < NT; t++) {
        const float4* xp = (const float4*)(x   + row_base + (size_t)t * NC * HW_);
        float4*       op = (float4*)      (out + row_base + (size_t)t * NC * HW_);

        const bool need_tau = (t < NT - 1);   // MLP needed for steps 0..6
        const bool need_P   = (t < NT - 2);   // P(t) used by MLP at t+1 <= 6

        // ---- 1) load x; mem = mem*tau + x (separate mul+add, JAX rounding);
        //         X partials (tau-free sums of x) in the same pass ----
        float partX[RPB];
        #pragma unroll
        for (int i = 0; i < RPB; i++) {
            float4 xv = __ldcs(xp + i * THREADS + tid);
            partX[i] = (xv.x + xv.y) + (xv.z + xv.w);
            float4 m = mem[i];
            m.x = __fadd_rn(__fmul_rn(m.x, tau), xv.x);
            m.y = __fadd_rn(__fmul_rn(m.y, tau), xv.y);
            m.z = __fadd_rn(__fmul_rn(m.z, tau), xv.z);
            m.w = __fadd_rn(__fmul_rn(m.w, tau), xv.w);
            mem[i] = m;
        }

        // ---- 2) publish X_c(t) ASAP (before the store phase) ----
        if (need_tau) {
            #pragma unroll
            for (int i = 0; i < RPB; i++) {
                float v = partX[i];
                v += __shfl_xor_sync(0xffffffffu, v, 16);
                v += __shfl_xor_sync(0xffffffffu, v, 8);
                v += __shfl_xor_sync(0xffffffffu, v, 4);
                v += __shfl_xor_sync(0xffffffffu, v, 2);
                v += __shfl_xor_sync(0xffffffffu, v, 1);
                if (lane == 0) s_warpX[warp][i] = v;
            }
            __syncthreads();
            if (tid < RPB) {
                float s = 0.f;
                #pragma unroll
                for (int w = 0; w < 8; w++) s += s_warpX[w][tid];
                __stcg(&g_X[t & 1][b * NC + sub * RPB + tid], s);
                red_release_add(&g_cntX[b], 1u);   // also releases prior P store
            }
        }

        // ---- 3) spike + output + soft reset; P partials of reset mem ----
        float partP[RPB];
        #pragma unroll
        for (int i = 0; i < RPB; i++) {
            float4 m = mem[i];
            float4 sp;
            sp.x = (m.x > 1.0f) ? 1.0f : 0.0f;
            sp.y = (m.y > 1.0f) ? 1.0f : 0.0f;
            sp.z = (m.z > 1.0f) ? 1.0f : 0.0f;
            sp.w = (m.w > 1.0f) ? 1.0f : 0.0f;
            __stcs(op + i * THREADS + tid, sp);
            m.x = (m.x > 1.0f) ? 0.0f : m.x;
            m.y = (m.y > 1.0f) ? 0.0f : m.y;
            m.z = (m.z > 1.0f) ? 0.0f : m.z;
            m.w = (m.w > 1.0f) ? 0.0f : m.w;
            mem[i] = m;
            partP[i] = (m.x + m.y) + (m.z + m.w);
        }

        if (!need_tau) break;

        // ---- 4) publish P_c(t) (consumed by the MLP at step t+1) ----
        if (need_P) {
            #pragma unroll
            for (int i = 0; i < RPB; i++) {
                float v = partP[i];
                v += __shfl_xor_sync(0xffffffffu, v, 16);
                v += __shfl_xor_sync(0xffffffffu, v, 8);
                v += __shfl_xor_sync(0xffffffffu, v, 4);
                v += __shfl_xor_sync(0xffffffffu, v, 2);
                v += __shfl_xor_sync(0xffffffffu, v, 1);
                if (lane == 0) s_warpP[warp][i] = v;
            }
            __syncthreads();
            if (tid < RPB) {
                float s = 0.f;
                #pragma unroll
                for (int w = 0; w < 8; w++) s += s_warpP[w][tid];
                // plain store: ordered by NEXT step's X release (same thread)
                __stcg(&g_P[t & 3][b * NC + sub * RPB + tid], s);
            }
        }

        // ---- 5) wait for all 16 blocks' X(t) (and, by program order,
        //         their P(t-1)); then local MLP -> tau_{t+1} ----
        if (tid == 0) {
            unsigned tgt = base_cnt + (unsigned)PUBS * (unsigned)(t + 1);
            while ((int)(ld_acquire(&g_cntX[b]) - tgt) < 0) { }
        }
        __syncthreads();

        if (tid < NC) {
            float Xc = __ldcg(&g_X[t & 1][b * NC + tid]);
            float Sc;
            if (t == 0) {
                Sc = Xc;    // P(-1)=0: bit-identical to elementwise sum
            } else {
                float Pc = __ldcg(&g_P[(t - 1) & 3][b * NC + tid]);
                Sc = __fadd_rn(__fmul_rn(tau, Pc), Xc);
            }
            s_mean[tid] = Sc * (1.0f / 1024.0f);
        }
        __syncthreads();
        if (tid < CR) {
            float acc = b1[tid];
            #pragma unroll
            for (int c = 0; c < NC; c++)
                acc = fmaf(s_w1[tid * NC + c], s_mean[c], acc);
            float e = fmaxf(acc, 0.0f);        // relu
            float p = e * w2[tid];
            p += __shfl_xor_sync(0xffffffffu, p, 16);
            p += __shfl_xor_sync(0xffffffffu, p, 8);
            p += __shfl_xor_sync(0xffffffffu, p, 4);
            p += __shfl_xor_sync(0xffffffffu, p, 2);
            p += __shfl_xor_sync(0xffffffffu, p, 1);
            if (tid == 0) {
                float z = p + b2[0];
                s_tau = 1.0f / (1.0f + expf(-z));   // sigmoid
            }
        }
        __syncthreads();
        tau = s_tau;
    }
}

extern "C" void kernel_launch(void* const* d_in, const int* in_sizes, int n_in,
                              void* d_out, int out_size)
{
    const float* x  = (const float*)d_in[0];
    const float* w1 = (const float*)d_in[1];
    const float* b1 = (const float*)d_in[2];
    const float* w2 = (const float*)d_in[3];
    const float* b2 = (const float*)d_in[4];
    float* out = (float*)d_out;

    lif_kernel<<<NBLOCKS, THREADS>>>(x, w1, b1, w2, b2, out);
}

// round 7
// speedup vs baseline: 1.5841x; 1.5841x over previous
#include <cuda_runtime.h>

// DynamicLIF persistent kernel for GB300 (sm_103a), round 7.
// = R1's RACE-FREE barrier (count -> leader -> gen release), restructured:
//   (a) leader releases g_gen IMMEDIATELY after all counts arrive (no MLP on
//       the serial chain), then ALL blocks run the tau-MLP redundantly;
//   (b) w1 cached TRANSPOSED in smem: old s_w1[r*128+c] put all 32 MLP
//       threads on one bank (32-way conflict, ~2us/step on the critical
//       path in R1). s_w1t[c*32+r] is conflict-free; values and fmaf order
//       unchanged -> tau bit-identical.
// The R3/R5/R6 monotonic-counter scheme is DEAD: its base-read races with
// peer publishes at startup (R6 deadlock). This scheme has no such race:
// each block reads base_gen before its first publish, and the leader cannot
// advance g_gen until every block has published.

#define NB 32          // batch
#define NT 8           // time steps
#define NC 128         // channels
#define HW_ 1024       // H*W
#define CR 32          // C / red
#define THREADS 256
#define RPB 8          // channel rows per block
#define BPB 16         // blocks per batch
#define NBLOCKS (NB * BPB)   // 512
#define PUBS (BPB * RPB)     // 128 count-releases per batch per step

__device__ float    g_sums[NB * NC];
__device__ unsigned g_count[NB];   // zero at launch; leader resets each round
__device__ unsigned g_gen[NB];     // monotonic across replays

__device__ __forceinline__ unsigned ld_acquire(const unsigned* p) {
    unsigned v;
    asm volatile("ld.acquire.gpu.global.u32 %0, [%1];" : "=r"(v) : "l"(p));
    return v;
}
__device__ __forceinline__ void red_release_add(unsigned* p, unsigned v) {
    asm volatile("red.release.gpu.global.add.u32 [%0], %1;" :: "l"(p), "r"(v));
}

__global__ void __launch_bounds__(THREADS, 4)
lif_kernel(const float* __restrict__ x,
           const float* __restrict__ w1,
           const float* __restrict__ b1,
           const float* __restrict__ w2,
           const float* __restrict__ b2,
           float* __restrict__ out)
{
    __shared__ float s_w1t[NC * CR];   // 16 KB, TRANSPOSED: [c][row]
    __shared__ float s_warp[8][RPB];
    __shared__ float s_mean[NC];
    __shared__ float s_tau;

    const int tid = threadIdx.x;
    const int blk = blockIdx.x;
    const int b   = blk >> 4;          // batch
    const int sub = blk & 15;          // sub-block within batch
    const bool leader = (sub == 0);
    const int lane = tid & 31;
    const int warp = tid >> 5;

    // Cache w1 transposed: s_w1t[c*CR + r] = w1[r*NC + c].
    #pragma unroll
    for (int i = 0; i < (CR * NC) / THREADS; i++) {
        int idx = i * THREADS + tid;   // linear over w1 (row-major r*NC+c)
        int r = idx >> 7;
        int c = idx & 127;
        s_w1t[c * CR + r] = w1[idx];
    }
    __syncthreads();

    // base_gen read precedes this block's first publish (program order),
    // and the leader cannot release gen until all 16 blocks publish ->
    // race-free across startup skew AND graph replays.
    unsigned base_gen = 0;
    if (tid == 0) base_gen = *(volatile unsigned*)&g_gen[b];

    float tau = 0.5f;                  // TAU0
    float4 mem[RPB];
    #pragma unroll
    for (int i = 0; i < RPB; i++) mem[i] = make_float4(0.f, 0.f, 0.f, 0.f);

    // This block owns channels [sub*RPB, sub*RPB+RPB) of batch b, all HW.
    const size_t row_base = ((size_t)b * NT * NC + (size_t)sub * RPB) * HW_;

    for (int t = 0; t < NT; t++) {
        const float4* xp = (const float4*)(x   + row_base + (size_t)t * NC * HW_);
        float4*       op = (float4*)      (out + row_base + (size_t)t * NC * HW_);

        // ---- 1) mem = mem*tau + x  (separate mul+add: matches JAX rounding),
        //         per-row partial sums. Bit-identical to R1. ----
        float part[RPB];
        #pragma unroll
        for (int i = 0; i < RPB; i++) {
            float4 xv = __ldcs(xp + i * THREADS + tid);
            float4 m = mem[i];
            m.x = __fadd_rn(__fmul_rn(m.x, tau), xv.x);
            m.y = __fadd_rn(__fmul_rn(m.y, tau), xv.y);
            m.z = __fadd_rn(__fmul_rn(m.z, tau), xv.z);
            m.w = __fadd_rn(__fmul_rn(m.w, tau), xv.w);
            mem[i] = m;
            part[i] = (m.x + m.y) + (m.z + m.w);
        }

        const bool need_tau = (t < NT - 1);   // last step: no MLP/barrier

        if (need_tau) {
            // Warp-reduce each row's partial (identical order to R1).
            #pragma unroll
            for (int i = 0; i < RPB; i++) {
                float v = part[i];
                v += __shfl_xor_sync(0xffffffffu, v, 16);
                v += __shfl_xor_sync(0xffffffffu, v, 8);
                v += __shfl_xor_sync(0xffffffffu, v, 4);
                v += __shfl_xor_sync(0xffffffffu, v, 2);
                v += __shfl_xor_sync(0xffffffffu, v, 1);
                if (lane == 0) s_warp[warp][i] = v;
            }
            __syncthreads();
            // Publish this block's 8 channel sums; release-count per storer.
            if (tid < RPB) {
                float s = 0.f;
                #pragma unroll
                for (int w = 0; w < 8; w++) s += s_warp[w][tid];
                __stcg(&g_sums[b * NC + sub * RPB + tid], s);
                red_release_add(&g_count[b], 1u);
            }
            // Leader: as soon as all 128 publishes arrive, reset the counter
            // and release the generation. NOTHING ELSE on the serial chain.
            if (leader && tid == 0) {
                while (ld_acquire(&g_count[b]) != (unsigned)PUBS) { }
                *(volatile unsigned*)&g_count[b] = 0;   // ordered by release below
                red_release_add(&g_gen[b], 1u);
            }
        }

        // ---- 2) spike + output + soft reset (overlaps barrier latency) ----
        #pragma unroll
        for (int i = 0; i < RPB; i++) {
            float4 m = mem[i];
            float4 sp;
            sp.x = (m.x > 1.0f) ? 1.0f : 0.0f;
            sp.y = (m.y > 1.0f) ? 1.0f : 0.0f;
            sp.z = (m.z > 1.0f) ? 1.0f : 0.0f;
            sp.w = (m.w > 1.0f) ? 1.0f : 0.0f;
            __stcs(op + i * THREADS + tid, sp);
            m.x = (m.x > 1.0f) ? 0.0f : m.x;
            m.y = (m.y > 1.0f) ? 0.0f : m.y;
            m.z = (m.z > 1.0f) ? 0.0f : m.z;
            m.w = (m.w > 1.0f) ? 0.0f : m.w;
            mem[i] = m;
        }

        if (!need_tau) break;

        // ---- 3) wait for the generation release (all sums visible) ----
        if (tid == 0) {
            unsigned tgt = base_gen + (unsigned)(t + 1);
            while ((int)(ld_acquire(&g_gen[b]) - tgt) < 0) { }
        }
        __syncthreads();

        // ---- 4) redundant per-block MLP, conflict-free smem access.
        //         Values + fmaf order bit-identical to R1's leader MLP. ----
        if (tid < NC)
            s_mean[tid] = __ldcg(&g_sums[b * NC + tid]) * (1.0f / 1024.0f);
        __syncthreads();
        if (tid < CR) {
            float acc = b1[tid];
            #pragma unroll
            for (int c = 0; c < NC; c++)
                acc = fmaf(s_w1t[c * CR + tid], s_mean[c], acc);   // bank = tid
            float e = fmaxf(acc, 0.0f);        // relu
            float p = e * w2[tid];
            p += __shfl_xor_sync(0xffffffffu, p, 16);
            p += __shfl_xor_sync(0xffffffffu, p, 8);
            p += __shfl_xor_sync(0xffffffffu, p, 4);
            p += __shfl_xor_sync(0xffffffffu, p, 2);
            p += __shfl_xor_sync(0xffffffffu, p, 1);
            if (tid == 0) {
                float z = p + b2[0];
                s_tau = 1.0f / (1.0f + expf(-z));   // sigmoid
            }
        }
        __syncthreads();
        tau = s_tau;
    }
}

extern "C" void kernel_launch(void* const* d_in, const int* in_sizes, int n_in,
                              void* d_out, int out_size)
{
    const float* x  = (const float*)d_in[0];
    const float* w1 = (const float*)d_in[1];
    const float* b1 = (const float*)d_in[2];
    const float* w2 = (const float*)d_in[3];
    const float* b2 = (const float*)d_in[4];
    float* out = (float*)d_out;

    lif_kernel<<<NBLOCKS, THREADS>>>(x, w1, b1, w2, b2, out);
}